// round 2
// baseline (speedup 1.0000x reference)
#include <cuda_runtime.h>
#include <cuda_bf16.h>

// CensoredLoss: outputs [B, T, V-1] f32, targets [B, T, V] f32, T=512, V=5.
// loss = sum_{b,t} [ tgt0*log(1 - sum(out) + EPS) + sum_v tgt_{v+1}*log(out_v + EPS) ]
// (mask is implicit: masked rows have all-zero targets -> zero contribution)
// count = sum_b (1 + max{t : sum_v targets[b,t,v] > 0})  (0 if none)
// result = count > 0 ? -loss/count : 0
//
// Single kernel: per-block accumulate -> global atomics -> last-block finalize
// (writes out[0] and resets accumulators for the next graph replay).

#define T_DIM 512
#define V_DIM 5
#define EPSF 1e-8f
#define NTHREADS 512

__device__ double             g_loss;    // zero-initialized at module load
__device__ unsigned long long g_count;
__device__ unsigned int       g_ticket;

__global__ __launch_bounds__(NTHREADS, 4)
void cl_main_kernel(const float* __restrict__ outputs,
                    const float* __restrict__ targets,
                    float* __restrict__ out,
                    int nblocks)
{
    __shared__ float s_tgt[T_DIM * V_DIM];       // 10240 B, one row of targets
    __shared__ float s_sum[NTHREADS / 32];
    __shared__ int   s_max[NTHREADS / 32];
    __shared__ bool  s_is_last;

    const int b   = blockIdx.x;
    const int tid = threadIdx.x;
    const int t   = tid;  // one timestep per thread

    // Prefetch this thread's outputs record (float4, 16B aligned) BEFORE the
    // staging loop so its DRAM latency overlaps the targets staging.
    const float4 o = __ldg(&reinterpret_cast<const float4*>(outputs)[(size_t)b * T_DIM + t]);

    // Stage this row's targets via fully-coalesced float4 loads.
    // Row base byte offset = b * 512 * 5 * 4 = b * 10240 -> 16B aligned.
    const float4* tg4 = reinterpret_cast<const float4*>(
        targets + (size_t)b * (T_DIM * V_DIM));
    float4* s4 = reinterpret_cast<float4*>(s_tgt);
    #pragma unroll
    for (int i = tid; i < (T_DIM * V_DIM) / 4; i += NTHREADS)
        s4[i] = tg4[i];
    __syncthreads();

    // 5-float target record from SMEM: bank = (5*lane + j) mod 32, conflict-free.
    const float t0 = s_tgt[t * 5 + 0];
    const float t1 = s_tgt[t * 5 + 1];
    const float t2 = s_tgt[t * 5 + 2];
    const float t3 = s_tgt[t * 5 + 3];
    const float t4 = s_tgt[t * 5 + 4];

    const float censor = 1.0f - (o.x + o.y + o.z + o.w);

    float c = t0 * __logf(censor + EPSF)
            + t1 * __logf(o.x + EPSF)
            + t2 * __logf(o.y + EPSF)
            + t3 * __logf(o.z + EPSF)
            + t4 * __logf(o.w + EPSF);

    // per_t > 0  (targets nonnegative; masked region is exactly 0)
    int last = ((t0 + t1 + t2 + t3 + t4) > 0.0f) ? t : -1;

    // Warp reduction
    #pragma unroll
    for (int off = 16; off > 0; off >>= 1) {
        c    += __shfl_down_sync(0xffffffffu, c, off);
        last  = max(last, __shfl_down_sync(0xffffffffu, last, off));
    }
    if ((tid & 31) == 0) {
        s_sum[tid >> 5] = c;
        s_max[tid >> 5] = last;
    }
    __syncthreads();

    // Final reduce across 16 warps (lanes 0..15 of warp 0), then global atomics.
    if (tid < NTHREADS / 32) {
        c    = s_sum[tid];
        last = s_max[tid];
        #pragma unroll
        for (int off = (NTHREADS / 64); off > 0; off >>= 1) {
            c    += __shfl_down_sync(0xffffu, c, off);
            last  = max(last, __shfl_down_sync(0xffffu, last, off));
        }
        if (tid == 0) {
            atomicAdd(&g_loss, (double)c);
            atomicAdd(&g_count, (unsigned long long)(last + 1));
            __threadfence();
            unsigned int tk = atomicAdd(&g_ticket, 1u);
            s_is_last = (tk == (unsigned int)(nblocks - 1));
        }
    }
    __syncthreads();

    // Last block finalizes: write the scalar and reset state for the next replay.
    if (s_is_last && tid == 0) {
        const double loss           = atomicAdd(&g_loss, 0.0);
        const unsigned long long ct = atomicAdd(&g_count, 0ULL);
        out[0] = (ct > 0ULL) ? (float)(-loss / (double)ct) : 0.0f;
        g_loss   = 0.0;
        g_count  = 0ULL;
        __threadfence();
        g_ticket = 0u;
    }
}

extern "C" void kernel_launch(void* const* d_in, const int* in_sizes, int n_in,
                              void* d_out, int out_size)
{
    const float* outputs = (const float*)d_in[0];
    const float* targets = (const float*)d_in[1];
    float* out = (float*)d_out;

    const int B = in_sizes[1] / (T_DIM * V_DIM);   // 16384

    cl_main_kernel<<<B, NTHREADS>>>(outputs, targets, out, B);
}

// round 4
// speedup vs baseline: 1.5000x; 1.5000x over previous
#include <cuda_runtime.h>
#include <cuda_bf16.h>

// CensoredLoss: outputs [B, T, V-1] f32, targets [B, T, V] f32, T=512, V=5.
// loss  = sum_{b,t} [ tgt0*log(1 - sum(out) + EPS) + sum_v tgt_{v+1}*log(out_v + EPS) ]
//         (masked rows have all-zero targets -> contribute exactly 0)
// count = sum_b (last_b + 1) = #{(b,t) : sum_v targets[b,t,v] > 0}   (valid prefix)
// result = count > 0 ? -loss/count : 0
//
// main: 2 rows/block, smem-staged targets, ballot-popc count, RED atomics.
// final: writes scalar AND resets accumulators (so no init kernel is needed).

#define T_DIM 512
#define V_DIM 5
#define RPB   2                       // rows per block
#define EPSF  1e-8f
#define NTHREADS 512

__device__ double       g_loss;       // zero at module load; finalize re-zeros
__device__ unsigned int g_count;

__global__ __launch_bounds__(NTHREADS, 4)
void cl_main_kernel(const float* __restrict__ outputs,
                    const float* __restrict__ targets)
{
    __shared__ float s_tgt[RPB * T_DIM * V_DIM];   // 20480 B, two rows of targets
    __shared__ float s_sum[NTHREADS / 32];
    __shared__ int   s_cnt[NTHREADS / 32];

    const int b0  = blockIdx.x * RPB;
    const int tid = threadIdx.x;
    const int t   = tid;                            // one timestep per thread per row

    // Prefetch both rows' outputs records (float4, 16B aligned) first so their
    // DRAM latency overlaps the targets staging.
    const float4* og4 = reinterpret_cast<const float4*>(outputs);
    const float4 o0 = og4[(size_t)(b0 + 0) * T_DIM + t];
    const float4 o1 = og4[(size_t)(b0 + 1) * T_DIM + t];

    // Stage 2 rows of targets via fully-coalesced float4 loads (rows adjacent).
    const float4* tg4 = reinterpret_cast<const float4*>(
        targets + (size_t)b0 * (T_DIM * V_DIM));
    float4* s4 = reinterpret_cast<float4*>(s_tgt);
    #pragma unroll
    for (int i = tid; i < (RPB * T_DIM * V_DIM) / 4; i += NTHREADS)
        s4[i] = tg4[i];
    __syncthreads();

    float c = 0.0f;
    int   nz0, nz1;
    {
        const float* p = s_tgt + t * 5;            // row 0 record (conflict-free: gcd(5,32)=1)
        const float t0 = p[0], t1 = p[1], t2 = p[2], t3 = p[3], t4 = p[4];
        const float censor = 1.0f - (o0.x + o0.y + o0.z + o0.w);
        c += t0 * __logf(censor + EPSF)
           + t1 * __logf(o0.x + EPSF)
           + t2 * __logf(o0.y + EPSF)
           + t3 * __logf(o0.z + EPSF)
           + t4 * __logf(o0.w + EPSF);
        nz0 = ((t0 + t1 + t2 + t3 + t4) > 0.0f);
    }
    {
        const float* p = s_tgt + (T_DIM * V_DIM) + t * 5;   // row 1 record
        const float t0 = p[0], t1 = p[1], t2 = p[2], t3 = p[3], t4 = p[4];
        const float censor = 1.0f - (o1.x + o1.y + o1.z + o1.w);
        c += t0 * __logf(censor + EPSF)
           + t1 * __logf(o1.x + EPSF)
           + t2 * __logf(o1.y + EPSF)
           + t3 * __logf(o1.z + EPSF)
           + t4 * __logf(o1.w + EPSF);
        nz1 = ((t0 + t1 + t2 + t3 + t4) > 0.0f);
    }

    // Warp reduce: float sum via shfl; count via two ballots + popc.
    int cnt = __popc(__ballot_sync(0xffffffffu, nz0))
            + __popc(__ballot_sync(0xffffffffu, nz1));
    #pragma unroll
    for (int off = 16; off > 0; off >>= 1)
        c += __shfl_down_sync(0xffffffffu, c, off);

    if ((tid & 31) == 0) {
        s_sum[tid >> 5] = c;
        s_cnt[tid >> 5] = cnt;
    }
    __syncthreads();

    // Final reduce across 16 warps (lanes 0..15 of warp 0), then RED atomics
    // (returns unused -> fire-and-forget reductions, no round-trip wait).
    if (tid < NTHREADS / 32) {
        c   = s_sum[tid];
        cnt = s_cnt[tid];
        #pragma unroll
        for (int off = (NTHREADS / 64); off > 0; off >>= 1) {
            c   += __shfl_down_sync(0xffffu, c, off);
            cnt += __shfl_down_sync(0xffffu, cnt, off);
        }
        if (tid == 0) {
            atomicAdd(&g_loss, (double)c);
            atomicAdd(&g_count, (unsigned int)cnt);
        }
    }
}

__global__ void cl_final_kernel(float* __restrict__ out) {
    const double loss      = g_loss;
    const unsigned int cnt = g_count;
    out[0] = (cnt > 0u) ? (float)(-loss / (double)cnt) : 0.0f;
    // Reset for the next graph replay (deterministic by induction).
    g_loss  = 0.0;
    g_count = 0u;
}

extern "C" void kernel_launch(void* const* d_in, const int* in_sizes, int n_in,
                              void* d_out, int out_size)
{
    const float* outputs = (const float*)d_in[0];
    const float* targets = (const float*)d_in[1];
    float* out = (float*)d_out;

    const int B = in_sizes[1] / (T_DIM * V_DIM);   // 16384

    cl_main_kernel<<<B / RPB, NTHREADS>>>(outputs, targets);
    cl_final_kernel<<<1, 1>>>(out);
}

// round 5
// speedup vs baseline: 1.5049x; 1.0033x over previous
#include <cuda_runtime.h>
#include <cuda_bf16.h>

// CensoredLoss: outputs [B, T, V-1] f32, targets [B, T, V] f32, T=512, V=5.
// loss  = sum_{b,t} [ tgt0*log(1 - sum(out) + EPS) + sum_v tgt_{v+1}*log(out_v + EPS) ]
//         (masked rows have all-zero targets -> contribute exactly 0)
// count = sum_b (last_b + 1) = #{(b,t) : sum_v targets[b,t,v] > 0}   (valid prefix)
// result = count > 0 ? -loss/count : 0
//
// main: 2 rows/block, smem-staged targets, ballot-popc count, RED atomics.
// final: launched with PDL (programmatic stream serialization) so its launch
//        latency overlaps the main kernel's tail; waits on griddepcontrol,
//        writes the scalar, and resets accumulators for the next graph replay.

#define T_DIM 512
#define V_DIM 5
#define RPB   2                       // rows per block
#define EPSF  1e-8f
#define NTHREADS 512

__device__ double       g_loss;       // zero at module load; finalize re-zeros
__device__ unsigned int g_count;

__global__ __launch_bounds__(NTHREADS, 4)
void cl_main_kernel(const float* __restrict__ outputs,
                    const float* __restrict__ targets)
{
    __shared__ float s_tgt[RPB * T_DIM * V_DIM];   // 20480 B, two rows of targets
    __shared__ float s_sum[NTHREADS / 32];
    __shared__ int   s_cnt[NTHREADS / 32];

    const int b0  = blockIdx.x * RPB;
    const int tid = threadIdx.x;
    const int t   = tid;                            // one timestep per thread per row

    // Prefetch both rows' outputs records (float4, 16B aligned) first so their
    // DRAM latency overlaps the targets staging.
    const float4* og4 = reinterpret_cast<const float4*>(outputs);
    const float4 o0 = og4[(size_t)(b0 + 0) * T_DIM + t];
    const float4 o1 = og4[(size_t)(b0 + 1) * T_DIM + t];

    // Stage 2 rows of targets via fully-coalesced float4 loads (rows adjacent).
    const float4* tg4 = reinterpret_cast<const float4*>(
        targets + (size_t)b0 * (T_DIM * V_DIM));
    float4* s4 = reinterpret_cast<float4*>(s_tgt);
    #pragma unroll
    for (int i = tid; i < (RPB * T_DIM * V_DIM) / 4; i += NTHREADS)
        s4[i] = tg4[i];
    __syncthreads();

    float c = 0.0f;
    int   nz0, nz1;
    {
        const float* p = s_tgt + t * 5;            // row 0 record (conflict-free: gcd(5,32)=1)
        const float t0 = p[0], t1 = p[1], t2 = p[2], t3 = p[3], t4 = p[4];
        const float censor = 1.0f - (o0.x + o0.y + o0.z + o0.w);
        c += t0 * __logf(censor + EPSF)
           + t1 * __logf(o0.x + EPSF)
           + t2 * __logf(o0.y + EPSF)
           + t3 * __logf(o0.z + EPSF)
           + t4 * __logf(o0.w + EPSF);
        nz0 = ((t0 + t1 + t2 + t3 + t4) > 0.0f);
    }
    {
        const float* p = s_tgt + (T_DIM * V_DIM) + t * 5;   // row 1 record
        const float t0 = p[0], t1 = p[1], t2 = p[2], t3 = p[3], t4 = p[4];
        const float censor = 1.0f - (o1.x + o1.y + o1.z + o1.w);
        c += t0 * __logf(censor + EPSF)
           + t1 * __logf(o1.x + EPSF)
           + t2 * __logf(o1.y + EPSF)
           + t3 * __logf(o1.z + EPSF)
           + t4 * __logf(o1.w + EPSF);
        nz1 = ((t0 + t1 + t2 + t3 + t4) > 0.0f);
    }

    // Warp reduce: float sum via shfl; count via two ballots + popc.
    int cnt = __popc(__ballot_sync(0xffffffffu, nz0))
            + __popc(__ballot_sync(0xffffffffu, nz1));
    #pragma unroll
    for (int off = 16; off > 0; off >>= 1)
        c += __shfl_down_sync(0xffffffffu, c, off);

    if ((tid & 31) == 0) {
        s_sum[tid >> 5] = c;
        s_cnt[tid >> 5] = cnt;
    }
    __syncthreads();

    // Final reduce across 16 warps (lanes 0..15 of warp 0), then RED atomics
    // (returns unused -> fire-and-forget reductions, no round-trip wait).
    if (tid < NTHREADS / 32) {
        c   = s_sum[tid];
        cnt = s_cnt[tid];
        #pragma unroll
        for (int off = (NTHREADS / 64); off > 0; off >>= 1) {
            c   += __shfl_down_sync(0xffffu, c, off);
            cnt += __shfl_down_sync(0xffffu, cnt, off);
        }
        if (tid == 0) {
            atomicAdd(&g_loss, (double)c);
            atomicAdd(&g_count, (unsigned int)cnt);
        }
    }
}

__global__ void cl_final_kernel(float* __restrict__ out) {
    // PDL: block until the upstream (main) grid has fully completed and its
    // memory operations are visible. With no explicit launch_dependents in the
    // main kernel, the trigger is implicit at grid end -> exact semantics; the
    // win is that this kernel's launch setup overlapped the main grid.
    asm volatile("griddepcontrol.wait;" ::: "memory");

    const double loss      = g_loss;
    const unsigned int cnt = g_count;
    out[0] = (cnt > 0u) ? (float)(-loss / (double)cnt) : 0.0f;
    // Reset for the next graph replay (deterministic by induction).
    g_loss  = 0.0;
    g_count = 0u;
}

extern "C" void kernel_launch(void* const* d_in, const int* in_sizes, int n_in,
                              void* d_out, int out_size)
{
    const float* outputs = (const float*)d_in[0];
    const float* targets = (const float*)d_in[1];
    float* out = (float*)d_out;

    const int B = in_sizes[1] / (T_DIM * V_DIM);   // 16384

    cl_main_kernel<<<B / RPB, NTHREADS>>>(outputs, targets);

    // Finalize with Programmatic Dependent Launch so its launch latency hides
    // under the main kernel instead of serializing after it.
    cudaLaunchConfig_t cfg = {};
    cfg.gridDim  = dim3(1, 1, 1);
    cfg.blockDim = dim3(1, 1, 1);
    cfg.dynamicSmemBytes = 0;
    cfg.stream = 0;  // legacy default stream (same one the <<<>>> launch used)
    cudaLaunchAttribute attrs[1];
    attrs[0].id = cudaLaunchAttributeProgrammaticStreamSerialization;
    attrs[0].val.programmaticStreamSerializationAllowed = 1;
    cfg.attrs    = attrs;
    cfg.numAttrs = 1;
    cudaLaunchKernelEx(&cfg, cl_final_kernel, out);
}